// round 2
// baseline (speedup 1.0000x reference)
#include <cuda_runtime.h>
#include <cuda_bf16.h>

#define L_SEQ 2048
#define NODE_DIM 64
#define EDGE_DIM 32
#define TPB 256
#define JPT (L_SEQ / TPB)   // 8 columns per thread

__global__ __launch_bounds__(TPB, 2) void se3_layer_kernel(
    const float* __restrict__ coords,      // (L,3)
    const float* __restrict__ nf,          // (L,64)
    const float* __restrict__ pf,          // (L,L,32)
    const float* __restrict__ w_attn,      // (33,1)
    const float* __restrict__ b_attn,      // (1,)
    const float* __restrict__ w_mag,       // (64,1)
    const float* __restrict__ b_mag,       // (1,)
    float* __restrict__ out)               // (L,3)
{
    __shared__ float sx[L_SEQ];
    __shared__ float sy[L_SEQ];
    __shared__ float sz[L_SEQ];
    __shared__ float sredmax[8];
    __shared__ float s4[8][4];
    __shared__ float smag;

    const int i    = blockIdx.x;
    const int t    = threadIdx.x;
    const int lane = t & 31;
    const int wid  = t >> 5;

    // Stage coords into shared (L2-hot after first wave).
    for (int j = t; j < L_SEQ; j += TPB) {
        sx[j] = coords[3 * j + 0];
        sy[j] = coords[3 * j + 1];
        sz[j] = coords[3 * j + 2];
    }

    // Warp 0: update magnitude for row i (independent of shared coords).
    if (wid == 0) {
        float m = nf[i * NODE_DIM + lane]      * w_mag[lane]
                + nf[i * NODE_DIM + 32 + lane] * w_mag[32 + lane];
        #pragma unroll
        for (int off = 16; off; off >>= 1)
            m += __shfl_xor_sync(0xffffffffu, m, off);
        if (lane == 0) smag = tanhf(m + b_mag[0]) * 0.1f;
    }
    __syncthreads();

    const float xi = sx[i], yi = sy[i], zi = sz[i];

    // Attention weights in registers (33 floats: 8 x float4 + scalar).
    const float4* wv = reinterpret_cast<const float4*>(w_attn);
    const float4 w0 = wv[0], w1 = wv[1], w2 = wv[2], w3 = wv[3];
    const float4 w4 = wv[4], w5 = wv[5], w6 = wv[6], w7 = wv[7];
    const float  wdist  = w_attn[32];
    const float  bconst = b_attn[0];

    const float4* pfr = reinterpret_cast<const float4*>(pf) + (size_t)i * L_SEQ * (EDGE_DIM / 4);

    // ---- Pass 1: logits (pair_features read, the only HBM-heavy pass) ----
    float lg[JPT];
    float lmax = -3.402823466e38f;
    #pragma unroll
    for (int k = 0; k < JPT; k++) {
        const int j = t + k * TPB;
        const float4* row = pfr + (size_t)j * (EDGE_DIM / 4);
        const float4 v0 = row[0], v1 = row[1], v2 = row[2], v3 = row[3];
        const float4 v4 = row[4], v5 = row[5], v6 = row[6], v7 = row[7];

        float acc;
        acc  = v0.x * w0.x + v0.y * w0.y + v0.z * w0.z + v0.w * w0.w;
        acc += v1.x * w1.x + v1.y * w1.y + v1.z * w1.z + v1.w * w1.w;
        acc += v2.x * w2.x + v2.y * w2.y + v2.z * w2.z + v2.w * w2.w;
        acc += v3.x * w3.x + v3.y * w3.y + v3.z * w3.z + v3.w * w3.w;
        acc += v4.x * w4.x + v4.y * w4.y + v4.z * w4.z + v4.w * w4.w;
        acc += v5.x * w5.x + v5.y * w5.y + v5.z * w5.z + v5.w * w5.w;
        acc += v6.x * w6.x + v6.y * w6.y + v6.z * w6.z + v6.w * w6.w;
        acc += v7.x * w7.x + v7.y * w7.y + v7.z * w7.z + v7.w * w7.w;

        const float dx = xi - sx[j];
        const float dy = yi - sy[j];
        const float dz = zi - sz[j];
        const float dist = sqrtf(dx * dx + dy * dy + dz * dz) + 1e-8f;

        const float l = acc + dist * wdist + bconst;
        lg[k] = l;
        lmax  = fmaxf(lmax, l);
    }

    // ---- Block max reduce ----
    #pragma unroll
    for (int off = 16; off; off >>= 1)
        lmax = fmaxf(lmax, __shfl_xor_sync(0xffffffffu, lmax, off));
    if (lane == 0) sredmax[wid] = lmax;
    __syncthreads();
    float bmax = sredmax[0];
    #pragma unroll
    for (int w = 1; w < 8; w++) bmax = fmaxf(bmax, sredmax[w]);

    // ---- Pass 2: exp + weighted direction sums (geometry recomputed from smem) ----
    float se = 0.f, ax = 0.f, ay = 0.f, az = 0.f;
    #pragma unroll
    for (int k = 0; k < JPT; k++) {
        const int j = t + k * TPB;
        const float e = __expf(lg[k] - bmax);
        const float dx = xi - sx[j];
        const float dy = yi - sy[j];
        const float dz = zi - sz[j];
        const float dist = sqrtf(dx * dx + dy * dy + dz * dz) + 1e-8f;
        const float w = e / dist;   // i==j: dx=dy=dz=0 -> contributes 0 to axes, e to se
        se += e;
        ax += w * dx;
        ay += w * dy;
        az += w * dz;
    }

    #pragma unroll
    for (int off = 16; off; off >>= 1) {
        se += __shfl_xor_sync(0xffffffffu, se, off);
        ax += __shfl_xor_sync(0xffffffffu, ax, off);
        ay += __shfl_xor_sync(0xffffffffu, ay, off);
        az += __shfl_xor_sync(0xffffffffu, az, off);
    }
    if (lane == 0) {
        s4[wid][0] = se; s4[wid][1] = ax; s4[wid][2] = ay; s4[wid][3] = az;
    }
    __syncthreads();

    if (t == 0) {
        float S = 0.f, X = 0.f, Y = 0.f, Z = 0.f;
        #pragma unroll
        for (int w = 0; w < 8; w++) {
            S += s4[w][0]; X += s4[w][1]; Y += s4[w][2]; Z += s4[w][3];
        }
        const float scale = smag / S;
        out[3 * i + 0] = xi + X * scale;
        out[3 * i + 1] = yi + Y * scale;
        out[3 * i + 2] = zi + Z * scale;
    }
}

extern "C" void kernel_launch(void* const* d_in, const int* in_sizes, int n_in,
                              void* d_out, int out_size)
{
    const float* coords = (const float*)d_in[0];
    const float* nf     = (const float*)d_in[1];
    const float* pf     = (const float*)d_in[2];
    const float* w_attn = (const float*)d_in[3];
    const float* b_attn = (const float*)d_in[4];
    const float* w_mag  = (const float*)d_in[5];
    const float* b_mag  = (const float*)d_in[6];
    float* out = (float*)d_out;

    se3_layer_kernel<<<L_SEQ, TPB>>>(coords, nf, pf, w_attn, b_attn, w_mag, b_mag, out);
}

// round 3
// speedup vs baseline: 1.6677x; 1.6677x over previous
#include <cuda_runtime.h>
#include <cuda_bf16.h>

#define L_SEQ 2048
#define NODE_DIM 64
#define EDGE_DIM 32
#define TPB 256
#define NWARP 8
#define NTILE 8          // 8 tiles x (8 warps x 32 rows) = 2048 rows

__global__ __launch_bounds__(TPB, 2) void se3_layer_kernel(
    const float* __restrict__ coords,      // (L,3)
    const float* __restrict__ nf,          // (L,64)
    const float* __restrict__ pf,          // (L,L,32)
    const float* __restrict__ w_attn,      // (33,1)
    const float* __restrict__ b_attn,      // (1,)
    const float* __restrict__ w_mag,       // (64,1)
    const float* __restrict__ b_mag,       // (1,)
    float* __restrict__ out)               // (L,3)
{
    __shared__ float sx[L_SEQ];
    __shared__ float sy[L_SEQ];
    __shared__ float sz[L_SEQ];
    __shared__ float sredmax[NWARP];
    __shared__ float s4[NWARP][4];
    __shared__ float smag;

    const int i    = blockIdx.x;
    const int t    = threadIdx.x;
    const int lane = t & 31;
    const int wid  = t >> 5;

    // Stage coords into shared (L2-hot after first wave).
    for (int j = t; j < L_SEQ; j += TPB) {
        sx[j] = coords[3 * j + 0];
        sy[j] = coords[3 * j + 1];
        sz[j] = coords[3 * j + 2];
    }

    // Warp 0: update magnitude for row i.
    if (wid == 0) {
        float m = nf[i * NODE_DIM + lane]      * w_mag[lane]
                + nf[i * NODE_DIM + 32 + lane] * w_mag[32 + lane];
        #pragma unroll
        for (int off = 16; off; off >>= 1)
            m += __shfl_xor_sync(0xffffffffu, m, off);
        if (lane == 0) smag = tanhf(m + b_mag[0]) * 0.1f;
    }
    __syncthreads();

    const float xi = sx[i], yi = sy[i], zi = sz[i];

    // Each lane holds ONE weight chunk (its l&7 position in the row).
    const float4* wv = reinterpret_cast<const float4*>(w_attn);
    const float4 wch   = wv[lane & 7];
    const float  wdist = w_attn[32];
    const float  bconst = b_attn[0];

    const float4* pfr = reinterpret_cast<const float4*>(pf)
                      + (size_t)i * L_SEQ * (EDGE_DIM / 4);

    // ---- Pass 1: coalesced cooperative logits ----
    // Warp-wide LDG.128: lane l reads float4 #(base + l): lanes 0-7 = row r0,
    // 8-15 = r0+1, ... -> 4 full lines per instruction, 1 wavefront per line.
    float lg[NTILE];
    float dst[NTILE];
    float lmax = -3.402823466e38f;

    #pragma unroll
    for (int tt = 0; tt < NTILE; tt++) {
        const int rowbase = tt * 256 + wid * 32;
        const float4* base = pfr + (size_t)rowbase * 8 + lane;

        // Front-load all 8 LDGs of this 32-row tile (MLP=8).
        float4 V[8];
        #pragma unroll
        for (int s = 0; s < 8; s++)
            V[s] = base[s * 32];     // +4 rows per step = +32 float4

        float dotv = 0.f;
        #pragma unroll
        for (int s = 0; s < 8; s++) {
            // Partial dot: this lane's chunk of row rowbase + 4*s + (lane>>3).
            float p = V[s].x * wch.x + V[s].y * wch.y
                    + V[s].z * wch.z + V[s].w * wch.w;
            // Sum across the 8-lane group sharing a row.
            p += __shfl_xor_sync(0xffffffffu, p, 1);
            p += __shfl_xor_sync(0xffffffffu, p, 2);
            p += __shfl_xor_sync(0xffffffffu, p, 4);
            // Redistribute: lane m owns row rowbase+m = rowbase+4*(m>>2)+(m&3),
            // produced at step s=m>>2 by group m&3 (source lane (m&3)<<3).
            const float q = __shfl_sync(0xffffffffu, p, (lane & 3) << 3);
            if ((lane >> 2) == s) dotv = q;
        }

        const int j = rowbase + lane;
        const float dx = xi - sx[j];
        const float dy = yi - sy[j];
        const float dz = zi - sz[j];
        const float d  = sqrtf(dx * dx + dy * dy + dz * dz) + 1e-8f;
        dst[tt] = d;
        const float l = dotv + d * wdist + bconst;
        lg[tt] = l;
        lmax   = fmaxf(lmax, l);
    }

    // ---- Block max reduce ----
    #pragma unroll
    for (int off = 16; off; off >>= 1)
        lmax = fmaxf(lmax, __shfl_xor_sync(0xffffffffu, lmax, off));
    if (lane == 0) sredmax[wid] = lmax;
    __syncthreads();
    float bmax = sredmax[0];
    #pragma unroll
    for (int w = 1; w < NWARP; w++) bmax = fmaxf(bmax, sredmax[w]);

    // ---- Pass 2: exp + weighted direction sums (registers + smem only) ----
    float se = 0.f, ax = 0.f, ay = 0.f, az = 0.f;
    #pragma unroll
    for (int tt = 0; tt < NTILE; tt++) {
        const int j = tt * 256 + wid * 32 + lane;
        const float e = __expf(lg[tt] - bmax);
        const float dx = xi - sx[j];
        const float dy = yi - sy[j];
        const float dz = zi - sz[j];
        const float w = __fdividef(e, dst[tt]);  // i==j: dx=dy=dz=0 -> axes get 0
        se += e;
        ax += w * dx;
        ay += w * dy;
        az += w * dz;
    }

    #pragma unroll
    for (int off = 16; off; off >>= 1) {
        se += __shfl_xor_sync(0xffffffffu, se, off);
        ax += __shfl_xor_sync(0xffffffffu, ax, off);
        ay += __shfl_xor_sync(0xffffffffu, ay, off);
        az += __shfl_xor_sync(0xffffffffu, az, off);
    }
    if (lane == 0) {
        s4[wid][0] = se; s4[wid][1] = ax; s4[wid][2] = ay; s4[wid][3] = az;
    }
    __syncthreads();

    if (t == 0) {
        float S = 0.f, X = 0.f, Y = 0.f, Z = 0.f;
        #pragma unroll
        for (int w = 0; w < NWARP; w++) {
            S += s4[w][0]; X += s4[w][1]; Y += s4[w][2]; Z += s4[w][3];
        }
        const float scale = smag / S;
        out[3 * i + 0] = xi + X * scale;
        out[3 * i + 1] = yi + Y * scale;
        out[3 * i + 2] = zi + Z * scale;
    }
}

extern "C" void kernel_launch(void* const* d_in, const int* in_sizes, int n_in,
                              void* d_out, int out_size)
{
    const float* coords = (const float*)d_in[0];
    const float* nf     = (const float*)d_in[1];
    const float* pf     = (const float*)d_in[2];
    const float* w_attn = (const float*)d_in[3];
    const float* b_attn = (const float*)d_in[4];
    const float* w_mag  = (const float*)d_in[5];
    const float* b_mag  = (const float*)d_in[6];
    float* out = (float*)d_out;

    se3_layer_kernel<<<L_SEQ, TPB>>>(coords, nf, pf, w_attn, b_attn, w_mag, b_mag, out);
}